// round 12
// baseline (speedup 1.0000x reference)
#include <cuda_runtime.h>

#define G       4
#define NPTS    40000
#define K       64
#define D       400
#define TILE_N  128
#define DKC     16
#define NBLK    148
#define BPG     37          // blocks per group (NBLK/4)
#define TILES   313         // ceil(40000/128)
#define EPOCHS  10
#define AS_STR  132         // A staging stride (floats)
#define BS_STR  68          // B staging stride
#define NCHUNK  (D / DKC)   // 25
#define NTHREADS 256

// Scratch (allocation-free: __device__ globals)
__device__ float g_centroids[G * K * D];
__device__ float g_c2[G * K];
__device__ float g_slab[(size_t)NBLK * K * D];   // per-block partial sums (~15 MB)
__device__ int   g_slabcnt[NBLK * K];

__device__ __forceinline__ unsigned long long pack2f(float x, float y) {
    unsigned long long r;
    asm("mov.b64 %0, {%1, %2};" : "=l"(r) : "f"(x), "f"(y));
    return r;
}
__device__ __forceinline__ void unpack2f(unsigned long long v, float& x, float& y) {
    asm("mov.b64 {%0, %1}, %2;" : "=f"(x), "=f"(y) : "l"(v));
}
// Packed dual-lane IEEE FMA: 2x FFMA throughput on sm_103a, bitwise == scalar fmaf per lane.
__device__ __forceinline__ void fma2(unsigned long long& d, unsigned long long a, unsigned long long b) {
    asm("fma.rn.f32x2 %0, %1, %2, %0;" : "+l"(d) : "l"(a), "l"(b));
}

__device__ __forceinline__ float block_reduce_sum_128(float v) {
    __shared__ float ws[4];
    #pragma unroll
    for (int o = 16; o > 0; o >>= 1) v += __shfl_down_sync(0xffffffffu, v, o);
    if ((threadIdx.x & 31) == 0) ws[threadIdx.x >> 5] = v;
    __syncthreads();
    float r = 0.f;
    if (threadIdx.x == 0) r = ws[0] + ws[1] + ws[2] + ws[3];
    return r;
}

// Copy initial centroids into working buffer + compute 0.5*||c||^2
__global__ void init_kernel(const float* __restrict__ cinit) {
    const int b = blockIdx.x;          // g*K + k
    const int tid = threadIdx.x;       // 128 threads
    const float* src = cinit + (size_t)b * D;
    float s = 0.f;
    for (int d = tid; d < D; d += 128) {
        float v = src[d];
        g_centroids[(size_t)b * D + d] = v;
        s += v * v;
    }
    s = block_reduce_sum_128(s);
    if (tid == 0) g_c2[b] = 0.5f * s;
}

// ───────────────────────────────────────────────────────────────────────────
// Fused hot kernel, 256 threads, 128-patch tiles, 4p x 8k k-packed microtile:
//   16 fma2 per 3 broadcast-dedup'd (conflict-free) LDS.128 + 4 movs.
//   Coalesced 4-lanes-per-row staging (8 L1 wavefronts/LDG.128), double
//   buffered (1 bar/chunk). Register argmax (8-lane shfl butterfly).
//   Accumulate unrolled 8-deep (MLP 8). No float atomics -> deterministic.
// Bitwise-identical arithmetic to the R5 baseline (same d-order, same tiles).
// ───────────────────────────────────────────────────────────────────────────
__global__ __launch_bounds__(NTHREADS, 1)
void assign_kernel(const float* __restrict__ patches) {
    extern __shared__ float sm[];
    float* part = sm;                           // K*D (100KB)
    float* As   = part + K * D;                 // 2*DKC*AS_STR
    float* Bs   = As + 2 * DKC * AS_STR;        // 2*DKC*BS_STR
    float* c2s  = Bs + 2 * DKC * BS_STR;        // K
    int* labels = (int*)(c2s + K);              // TILE_N
    __shared__ int cnt[K];

    const int b   = blockIdx.x;
    const int g   = b & 3;
    const int bg  = b >> 2;
    const int tid = threadIdx.x;
    const int tx  = tid & 7;        // centroid micro-dim: k = tx*8 + j (j 0..7)
    const int ty  = tid >> 3;       // patch micro-dim (0..31): p = ty*4 + i
    const int lp  = tid >> 2;       // staging row 0..63
    const int lq  = tid & 3;        // staging quad 0..3

    for (int i = tid; i < K * D; i += NTHREADS) part[i] = 0.f;
    if (tid < K) { cnt[tid] = 0; c2s[tid] = g_c2[g * K + tid]; }
    __syncthreads();

    // B staging source: centroid row lp (0..63), quad lq. Coalesced 64B/row.
    const float* Bsrc = g_centroids + (size_t)(g * K + lp) * D + lq * 4;

#define STAGE(bufi, ra0, ra1, rb) do {                                       \
        float* a_ = As + (bufi) * (DKC * AS_STR);                            \
        a_[(lq * 4 + 0) * AS_STR + lp] = (ra0).x;                            \
        a_[(lq * 4 + 1) * AS_STR + lp] = (ra0).y;                            \
        a_[(lq * 4 + 2) * AS_STR + lp] = (ra0).z;                            \
        a_[(lq * 4 + 3) * AS_STR + lp] = (ra0).w;                            \
        a_[(lq * 4 + 0) * AS_STR + lp + 64] = (ra1).x;                       \
        a_[(lq * 4 + 1) * AS_STR + lp + 64] = (ra1).y;                       \
        a_[(lq * 4 + 2) * AS_STR + lp + 64] = (ra1).z;                       \
        a_[(lq * 4 + 3) * AS_STR + lp + 64] = (ra1).w;                       \
        float* b_ = Bs + (bufi) * (DKC * BS_STR);                            \
        b_[(lq * 4 + 0) * BS_STR + lp] = (rb).x;                            \
        b_[(lq * 4 + 1) * BS_STR + lp] = (rb).y;                            \
        b_[(lq * 4 + 2) * BS_STR + lp] = (rb).z;                            \
        b_[(lq * 4 + 3) * BS_STR + lp] = (rb).w;                            \
    } while (0)

    for (int t = bg; t < TILES; t += BPG) {
        const int n0   = t * TILE_N;
        const int nrem = min(TILE_N, NPTS - n0);

        // A staging: patch rows lp and lp+64, quad lq (4 lanes/row, coalesced)
        const float* A0src = (lp < nrem)
            ? (patches + ((size_t)(n0 + lp) * G + g) * D + lq * 4) : (const float*)0;
        const float* A1src = (lp + 64 < nrem)
            ? (patches + ((size_t)(n0 + lp + 64) * G + g) * D + lq * 4) : (const float*)0;

        // prologue: chunk 0 -> buffer 0
        float4 ra0 = A0src ? *(const float4*)A0src : make_float4(0.f, 0.f, 0.f, 0.f);
        float4 ra1 = A1src ? *(const float4*)A1src : make_float4(0.f, 0.f, 0.f, 0.f);
        float4 rb  = *(const float4*)Bsrc;
        STAGE(0, ra0, ra1, rb);
        __syncthreads();

        // acc[i][jp]: patch ty*4+i vs packed centroid pair (tx*8+2jp, tx*8+2jp+1).
        // Seeded with -0.5*||c||^2 so argmax needs no epilogue subtract.
        unsigned long long acc[4][4];
        #pragma unroll
        for (int jp = 0; jp < 4; jp++) {
            unsigned long long pv = pack2f(-c2s[tx * 8 + 2 * jp], -c2s[tx * 8 + 2 * jp + 1]);
            #pragma unroll
            for (int i = 0; i < 4; i++) acc[i][jp] = pv;
        }

        #pragma unroll 1
        for (int c = 0; c < NCHUNK; ++c) {
            if (c + 1 < NCHUNK) {   // prefetch next chunk global -> regs
                const int off = (c + 1) * DKC;
                ra0 = A0src ? *(const float4*)(A0src + off) : make_float4(0.f, 0.f, 0.f, 0.f);
                ra1 = A1src ? *(const float4*)(A1src + off) : make_float4(0.f, 0.f, 0.f, 0.f);
                rb  = *(const float4*)(Bsrc + off);
            }
            const float* a_ = As + (c & 1) * (DKC * AS_STR);
            const float* b_ = Bs + (c & 1) * (DKC * BS_STR);
            #pragma unroll 8
            for (int kk = 0; kk < DKC; kk++) {
                // A: 4 distinct 16B (broadcast x8) = 64B; B: 8 distinct x2 = 128B each.
                const float4 av = *(const float4*)(a_ + kk * AS_STR + ty * 4);
                const float4 b0 = *(const float4*)(b_ + kk * BS_STR + tx * 8);
                const float4 b1 = *(const float4*)(b_ + kk * BS_STR + tx * 8 + 4);
                unsigned long long ap[4], bd[4];
                ap[0] = pack2f(av.x, av.x);
                ap[1] = pack2f(av.y, av.y);
                ap[2] = pack2f(av.z, av.z);
                ap[3] = pack2f(av.w, av.w);
                bd[0] = pack2f(b0.x, b0.y);   // native k-pairs: no dup movs
                bd[1] = pack2f(b0.z, b0.w);
                bd[2] = pack2f(b1.x, b1.y);
                bd[3] = pack2f(b1.z, b1.w);
                #pragma unroll
                for (int i = 0; i < 4; i++)
                    #pragma unroll
                    for (int jp = 0; jp < 4; jp++)
                        fma2(acc[i][jp], ap[i], bd[jp]);
            }
            if (c + 1 < NCHUNK) {
                STAGE((c + 1) & 1, ra0, ra1, rb);
                __syncthreads();
            }
        }

        // Register argmax per patch: local first-max over this thread's 8 k,
        // then 8-lane shfl_xor butterfly across tx (lane bits 0..2).
        // Merge = lexicographic max on (value, smaller k): reproduces
        // jnp.argmax first-occurrence ties. Associative + idempotent.
        #pragma unroll
        for (int i = 0; i < 4; i++) {
            float v[8];
            #pragma unroll
            for (int jp = 0; jp < 4; jp++) unpack2f(acc[i][jp], v[2 * jp], v[2 * jp + 1]);
            float bb = v[0];
            int   bk = tx * 8;
            #pragma unroll
            for (int j = 1; j < 8; j++)
                if (v[j] > bb) { bb = v[j]; bk = tx * 8 + j; }
            #pragma unroll
            for (int o = 1; o < 8; o <<= 1) {
                float ov = __shfl_xor_sync(0xffffffffu, bb, o);
                int   ok = __shfl_xor_sync(0xffffffffu, bk, o);
                if (ov > bb || (ov == bb && ok < bk)) { bb = ov; bk = ok; }
            }
            if (tx == 0) {
                const int p = ty * 4 + i;
                if (p < nrem) { labels[p] = bk; atomicAdd(&cnt[bk], 1); }
            }
        }
        __syncthreads();

        // Fused accumulate (patch rows L1/L2-hot from the GEMM stream).
        // 8 patches per iteration: 8 label LDS + up to 16 LDG in flight before
        // any smem RMW -> MLP 8 vs the old 2 (this phase was latency-exposed).
        {
            const bool two = (tid < D - 256);
            int p = 0;
            for (; p + 8 <= nrem; p += 8) {
                int lb[8];
                #pragma unroll
                for (int u = 0; u < 8; u++) lb[u] = labels[p + u];
                float va[8], vb[8];
                #pragma unroll
                for (int u = 0; u < 8; u++) {
                    const float* pr = patches + ((size_t)(n0 + p + u) * G + g) * D;
                    va[u] = pr[tid];
                    vb[u] = two ? pr[tid + 256] : 0.f;
                }
                #pragma unroll
                for (int u = 0; u < 8; u++) {
                    float* dst = part + lb[u] * D;
                    dst[tid] += va[u];
                    if (two) dst[tid + 256] += vb[u];
                }
            }
            for (; p < nrem; ++p) {
                const float* pr = patches + ((size_t)(n0 + p) * G + g) * D;
                float* dst = part + labels[p] * D;
                dst[tid] += pr[tid];
                if (two) dst[tid + 256] += pr[tid + 256];
            }
        }
        __syncthreads();
    }
#undef STAGE

    for (int i = tid; i < K * D; i += NTHREADS) g_slab[(size_t)b * (K * D) + i] = part[i];
    if (tid < K) g_slabcnt[b * K + tid] = cnt[tid];
}

// Deterministic slab reduction + centroid update (+ empty-cluster rule) + next c2.
__global__ void update_kernel() {
    const int b = blockIdx.x;        // g*K + k
    const int g = b >> 6;
    const int k = b & 63;
    const int tid = threadIdx.x;     // 128 threads
    __shared__ int scnt[G];
    if (tid < G) {
        int c = 0;
        for (int j = 0; j < BPG; j++) c += g_slabcnt[(tid + 4 * j) * K + k];
        scnt[tid] = c;
    }
    __syncthreads();
    const bool bad = (scnt[0] == 0) | (scnt[1] == 0) | (scnt[2] == 0) | (scnt[3] == 0);
    const int cn = scnt[g];
    const float cf = (float)(cn == 0 ? 1 : cn);
    float ss = 0.f;
    for (int d = tid; d < D; d += 128) {
        float s = 0.f;
        for (int j = 0; j < BPG; j++)
            s += g_slab[(size_t)(g + 4 * j) * (K * D) + k * D + d];
        float v = bad ? 0.f : (s / cf);
        g_centroids[(size_t)b * D + d] = v;
        ss += v * v;
    }
    ss = block_reduce_sum_128(ss);
    if (tid == 0) g_c2[b] = 0.5f * ss;
}

__global__ void copy_out_kernel(float* __restrict__ out) {
    int i = blockIdx.x * 256 + threadIdx.x;
    if (i < G * K * D) out[i] = g_centroids[i];
}

extern "C" void kernel_launch(void* const* d_in, const int* in_sizes, int n_in,
                              void* d_out, int out_size) {
    const float* patches = (const float*)d_in[0];
    const float* cinit   = (const float*)d_in[1];
    if (n_in >= 2 && in_sizes[0] == G * K * D && in_sizes[1] != G * K * D) {
        patches = (const float*)d_in[1];
        cinit   = (const float*)d_in[0];
    }
    float* out = (float*)d_out;

    const int SMEM_BYTES =
        (K * D + 2 * DKC * AS_STR + 2 * DKC * BS_STR + K + TILE_N) * 4; // 128768
    cudaFuncSetAttribute(assign_kernel, cudaFuncAttributeMaxDynamicSharedMemorySize, SMEM_BYTES);

    init_kernel<<<G * K, 128>>>(cinit);
    for (int e = 0; e < EPOCHS; e++) {
        assign_kernel<<<NBLK, NTHREADS, SMEM_BYTES>>>(patches);
        update_kernel<<<G * K, 128>>>();
    }
    copy_out_kernel<<<(G * K * D + 255) / 256, 256>>>(out);
}

// round 14
// speedup vs baseline: 1.0566x; 1.0566x over previous
#include <cuda_runtime.h>

#define G       4
#define NPTS    40000
#define K       64
#define D       400
#define TILE_N  128
#define DKC     16
#define NBLK    148
#define BPG     37          // blocks per group (NBLK/4)
#define TILES   313         // ceil(40000/128)
#define EPOCHS  10
#define AS_STR  132         // A staging stride (floats)
#define BS_STR  68          // B staging stride
#define NCHUNK  (D / DKC)   // 25
#define NTHREADS 256

// Scratch (allocation-free: __device__ globals)
__device__ float g_centroids[G * K * D];
__device__ float g_c2[G * K];
__device__ float g_slab[(size_t)NBLK * K * D];   // per-block partial sums (~15 MB)
__device__ int   g_slabcnt[NBLK * K];

__device__ __forceinline__ unsigned long long pack2f(float x, float y) {
    unsigned long long r;
    asm("mov.b64 %0, {%1, %2};" : "=l"(r) : "f"(x), "f"(y));
    return r;
}
__device__ __forceinline__ void unpack2f(unsigned long long v, float& x, float& y) {
    asm("mov.b64 {%0, %1}, %2;" : "=f"(x), "=f"(y) : "l"(v));
}
// Packed dual-lane IEEE FMA: 2x FFMA throughput on sm_103a, bitwise == scalar fmaf per lane.
__device__ __forceinline__ void fma2(unsigned long long& d, unsigned long long a, unsigned long long b) {
    asm("fma.rn.f32x2 %0, %1, %2, %0;" : "+l"(d) : "l"(a), "l"(b));
}

__device__ __forceinline__ float block_reduce_sum_128(float v) {
    __shared__ float ws[4];
    #pragma unroll
    for (int o = 16; o > 0; o >>= 1) v += __shfl_down_sync(0xffffffffu, v, o);
    if ((threadIdx.x & 31) == 0) ws[threadIdx.x >> 5] = v;
    __syncthreads();
    float r = 0.f;
    if (threadIdx.x == 0) r = ws[0] + ws[1] + ws[2] + ws[3];
    return r;
}

// Copy initial centroids into working buffer + compute 0.5*||c||^2
__global__ void init_kernel(const float* __restrict__ cinit) {
    const int b = blockIdx.x;          // g*K + k
    const int tid = threadIdx.x;       // 128 threads
    const float* src = cinit + (size_t)b * D;
    float s = 0.f;
    for (int d = tid; d < D; d += 128) {
        float v = src[d];
        g_centroids[(size_t)b * D + d] = v;
        s += v * v;
    }
    s = block_reduce_sum_128(s);
    if (tid == 0) g_c2[b] = 0.5f * s;
}

// ───────────────────────────────────────────────────────────────────────────
// Fused hot kernel, 256 threads, 128-patch tiles, 4p x 8k microtile.
// New this round: global prefetch DISTANCE 2 (breaks the per-chunk barrier
// convoy on DRAM latency) + software-pipelined LDS (29-cyc latency covered
// by construction). Accumulate back to the validated 2-deep form (no spill).
// No float atomics -> deterministic. Arithmetic order identical to R5/R12.
// ───────────────────────────────────────────────────────────────────────────
__global__ __launch_bounds__(NTHREADS, 1)
void assign_kernel(const float* __restrict__ patches) {
    extern __shared__ float sm[];
    float* part = sm;                           // K*D (100KB)
    float* As   = part + K * D;                 // 2*DKC*AS_STR
    float* Bs   = As + 2 * DKC * AS_STR;        // 2*DKC*BS_STR
    float* c2s  = Bs + 2 * DKC * BS_STR;        // K
    int* labels = (int*)(c2s + K);              // TILE_N
    __shared__ int cnt[K];

    const int b   = blockIdx.x;
    const int g   = b & 3;
    const int bg  = b >> 2;
    const int tid = threadIdx.x;
    const int tx  = tid & 7;        // centroid micro-dim: k = tx*8 + j (j 0..7)
    const int ty  = tid >> 3;       // patch micro-dim (0..31): p = ty*4 + i
    const int lp  = tid >> 2;       // staging row 0..63
    const int lq  = tid & 3;        // staging quad 0..3

    for (int i = tid; i < K * D; i += NTHREADS) part[i] = 0.f;
    if (tid < K) { cnt[tid] = 0; c2s[tid] = g_c2[g * K + tid]; }
    __syncthreads();

    // B staging source: centroid row lp (0..63), quad lq. Coalesced 64B/row.
    const float* Bsrc = g_centroids + (size_t)(g * K + lp) * D + lq * 4;

#define STAGE(bufi, ra0, ra1, rb) do {                                       \
        float* a_ = As + (bufi) * (DKC * AS_STR);                            \
        a_[(lq * 4 + 0) * AS_STR + lp] = (ra0).x;                            \
        a_[(lq * 4 + 1) * AS_STR + lp] = (ra0).y;                            \
        a_[(lq * 4 + 2) * AS_STR + lp] = (ra0).z;                            \
        a_[(lq * 4 + 3) * AS_STR + lp] = (ra0).w;                            \
        a_[(lq * 4 + 0) * AS_STR + lp + 64] = (ra1).x;                       \
        a_[(lq * 4 + 1) * AS_STR + lp + 64] = (ra1).y;                       \
        a_[(lq * 4 + 2) * AS_STR + lp + 64] = (ra1).z;                       \
        a_[(lq * 4 + 3) * AS_STR + lp + 64] = (ra1).w;                       \
        float* b_ = Bs + (bufi) * (DKC * BS_STR);                            \
        b_[(lq * 4 + 0) * BS_STR + lp] = (rb).x;                            \
        b_[(lq * 4 + 1) * BS_STR + lp] = (rb).y;                            \
        b_[(lq * 4 + 2) * BS_STR + lp] = (rb).z;                            \
        b_[(lq * 4 + 3) * BS_STR + lp] = (rb).w;                            \
    } while (0)

#define LDGCHUNK(si, cc) do {                                                \
        const int off_ = (cc) * DKC;                                         \
        pra0[si] = A0src ? *(const float4*)(A0src + off_)                    \
                         : make_float4(0.f, 0.f, 0.f, 0.f);                  \
        pra1[si] = A1src ? *(const float4*)(A1src + off_)                    \
                         : make_float4(0.f, 0.f, 0.f, 0.f);                  \
        prb[si]  = *(const float4*)(Bsrc + off_);                            \
    } while (0)

    for (int t = bg; t < TILES; t += BPG) {
        const int n0   = t * TILE_N;
        const int nrem = min(TILE_N, NPTS - n0);

        // A staging: patch rows lp and lp+64, quad lq (4 lanes/row, coalesced)
        const float* A0src = (lp < nrem)
            ? (patches + ((size_t)(n0 + lp) * G + g) * D + lq * 4) : (const float*)0;
        const float* A1src = (lp + 64 < nrem)
            ? (patches + ((size_t)(n0 + lp + 64) * G + g) * D + lq * 4) : (const float*)0;

        // prologue: chunk0 -> set0 -> buf0; chunk1 -> set1 (staged at end of c=0)
        float4 pra0[2], pra1[2], prb[2];
        LDGCHUNK(0, 0);
        STAGE(0, pra0[0], pra1[0], prb[0]);
        LDGCHUNK(1, 1);
        __syncthreads();

        // acc[i][jp]: patch ty*4+i vs packed centroid pair (tx*8+2jp, tx*8+2jp+1).
        // Seeded with -0.5*||c||^2 so argmax needs no epilogue subtract.
        unsigned long long acc[4][4];
        #pragma unroll
        for (int jp = 0; jp < 4; jp++) {
            unsigned long long pv = pack2f(-c2s[tx * 8 + 2 * jp], -c2s[tx * 8 + 2 * jp + 1]);
            #pragma unroll
            for (int i = 0; i < 4; i++) acc[i][jp] = pv;
        }

        #pragma unroll 1
        for (int c = 0; c < NCHUNK; ++c) {
            const int s = c & 1;
            // prefetch distance 2: chunk c+2 into the set freed when chunk c
            // was staged (end of iteration c-1). Its STS happens at the end of
            // iteration c+1 -> ~2 chunk-times of latency budget.
            if (c + 2 < NCHUNK) LDGCHUNK(s, c + 2);

            const float* a_ = As + s * (DKC * AS_STR);
            const float* b_ = Bs + s * (DKC * BS_STR);

            // software-pipelined LDS: load kk+1 while computing kk
            float4 av = *(const float4*)(a_ + ty * 4);
            float4 b0 = *(const float4*)(b_ + tx * 8);
            float4 b1 = *(const float4*)(b_ + tx * 8 + 4);
            #pragma unroll
            for (int kk = 0; kk < DKC; kk++) {
                float4 nav, nb0, nb1;
                if (kk + 1 < DKC) {
                    nav = *(const float4*)(a_ + (kk + 1) * AS_STR + ty * 4);
                    nb0 = *(const float4*)(b_ + (kk + 1) * BS_STR + tx * 8);
                    nb1 = *(const float4*)(b_ + (kk + 1) * BS_STR + tx * 8 + 4);
                }
                unsigned long long ap[4], bd[4];
                ap[0] = pack2f(av.x, av.x);
                ap[1] = pack2f(av.y, av.y);
                ap[2] = pack2f(av.z, av.z);
                ap[3] = pack2f(av.w, av.w);
                bd[0] = pack2f(b0.x, b0.y);   // native k-pairs: no dup movs
                bd[1] = pack2f(b0.z, b0.w);
                bd[2] = pack2f(b1.x, b1.y);
                bd[3] = pack2f(b1.z, b1.w);
                #pragma unroll
                for (int i = 0; i < 4; i++)
                    #pragma unroll
                    for (int jp = 0; jp < 4; jp++)
                        fma2(acc[i][jp], ap[i], bd[jp]);
                if (kk + 1 < DKC) { av = nav; b0 = nb0; b1 = nb1; }
            }
            if (c + 1 < NCHUNK) {
                const int s1 = (c + 1) & 1;
                STAGE(s1, pra0[s1], pra1[s1], prb[s1]);
                __syncthreads();
            }
        }

        // Register argmax per patch: local first-max over this thread's 8 k,
        // then 8-lane shfl_xor butterfly across tx (lane bits 0..2).
        // Merge = lexicographic max on (value, smaller k): reproduces
        // jnp.argmax first-occurrence ties. Associative + idempotent.
        #pragma unroll
        for (int i = 0; i < 4; i++) {
            float v[8];
            #pragma unroll
            for (int jp = 0; jp < 4; jp++) unpack2f(acc[i][jp], v[2 * jp], v[2 * jp + 1]);
            float bb = v[0];
            int   bk = tx * 8;
            #pragma unroll
            for (int j = 1; j < 8; j++)
                if (v[j] > bb) { bb = v[j]; bk = tx * 8 + j; }
            #pragma unroll
            for (int o = 1; o < 8; o <<= 1) {
                float ov = __shfl_xor_sync(0xffffffffu, bb, o);
                int   ok = __shfl_xor_sync(0xffffffffu, bk, o);
                if (ov > bb || (ov == bb && ok < bk)) { bb = ov; bk = ok; }
            }
            if (tx == 0) {
                const int p = ty * 4 + i;
                if (p < nrem) { labels[p] = bk; atomicAdd(&cnt[bk], 1); }
            }
        }
        __syncthreads();

        // Fused accumulate (validated 2-deep form; patch rows L1/L2-hot).
        {
            const bool two = (tid < D - 256);
            int p = 0;
            for (; p + 1 < nrem; p += 2) {
                const int l0 = labels[p];
                const int l1 = labels[p + 1];
                const float* prow0 = patches + ((size_t)(n0 + p    ) * G + g) * D;
                const float* prow1 = patches + ((size_t)(n0 + p + 1) * G + g) * D;
                const float v0a = prow0[tid];
                const float v1a = prow1[tid];
                float v0b = 0.f, v1b = 0.f;
                if (two) { v0b = prow0[tid + 256]; v1b = prow1[tid + 256]; }
                float* dst0 = part + l0 * D;
                float* dst1 = part + l1 * D;
                dst0[tid] += v0a;
                if (two) dst0[tid + 256] += v0b;
                dst1[tid] += v1a;
                if (two) dst1[tid + 256] += v1b;
            }
            if (p < nrem) {
                const float* prow = patches + ((size_t)(n0 + p) * G + g) * D;
                float* dst = part + labels[p] * D;
                dst[tid] += prow[tid];
                if (two) dst[tid + 256] += prow[tid + 256];
            }
        }
        __syncthreads();
    }
#undef STAGE
#undef LDGCHUNK

    for (int i = tid; i < K * D; i += NTHREADS) g_slab[(size_t)b * (K * D) + i] = part[i];
    if (tid < K) g_slabcnt[b * K + tid] = cnt[tid];
}

// Deterministic slab reduction + centroid update (+ empty-cluster rule) + next c2.
__global__ void update_kernel() {
    const int b = blockIdx.x;        // g*K + k
    const int g = b >> 6;
    const int k = b & 63;
    const int tid = threadIdx.x;     // 128 threads
    __shared__ int scnt[G];
    if (tid < G) {
        int c = 0;
        for (int j = 0; j < BPG; j++) c += g_slabcnt[(tid + 4 * j) * K + k];
        scnt[tid] = c;
    }
    __syncthreads();
    const bool bad = (scnt[0] == 0) | (scnt[1] == 0) | (scnt[2] == 0) | (scnt[3] == 0);
    const int cn = scnt[g];
    const float cf = (float)(cn == 0 ? 1 : cn);
    float ss = 0.f;
    for (int d = tid; d < D; d += 128) {
        float s = 0.f;
        for (int j = 0; j < BPG; j++)
            s += g_slab[(size_t)(g + 4 * j) * (K * D) + k * D + d];
        float v = bad ? 0.f : (s / cf);
        g_centroids[(size_t)b * D + d] = v;
        ss += v * v;
    }
    ss = block_reduce_sum_128(ss);
    if (tid == 0) g_c2[b] = 0.5f * ss;
}

__global__ void copy_out_kernel(float* __restrict__ out) {
    int i = blockIdx.x * 256 + threadIdx.x;
    if (i < G * K * D) out[i] = g_centroids[i];
}

extern "C" void kernel_launch(void* const* d_in, const int* in_sizes, int n_in,
                              void* d_out, int out_size) {
    const float* patches = (const float*)d_in[0];
    const float* cinit   = (const float*)d_in[1];
    if (n_in >= 2 && in_sizes[0] == G * K * D && in_sizes[1] != G * K * D) {
        patches = (const float*)d_in[1];
        cinit   = (const float*)d_in[0];
    }
    float* out = (float*)d_out;

    const int SMEM_BYTES =
        (K * D + 2 * DKC * AS_STR + 2 * DKC * BS_STR + K + TILE_N) * 4; // 128768
    cudaFuncSetAttribute(assign_kernel, cudaFuncAttributeMaxDynamicSharedMemorySize, SMEM_BYTES);

    init_kernel<<<G * K, 128>>>(cinit);
    for (int e = 0; e < EPOCHS; e++) {
        assign_kernel<<<NBLK, NTHREADS, SMEM_BYTES>>>(patches);
        update_kernel<<<G * K, 128>>>();
    }
    copy_out_kernel<<<(G * K * D + 255) / 256, 256>>>(out);
}